// round 14
// baseline (speedup 1.0000x reference)
#include <cuda_runtime.h>

// CfC recurrent kernel, round 14: R13 (counted-mbarrier cluster exchange)
// + exit-safety fix: skip last-step h-push and add a final cluster barrier
// so no remote DSMEM op can target an exited CTA. B=256, S=2048, C=64,
// U=128, H=256. 32 clusters x 4 CTAs x 256 threads; CTA rank holds
// W0[:,64r:+64) (48KB) + interleaved head quads for units [32r,+32) (128KB);
// 48/64 GEMM2 k-slices pinned in registers. Packed fp32x2 FMA.

typedef unsigned long long u64;

#define S_LEN 2048
#define NTHRD 256
#define KREG 48

// SMEM layout (u64 units)
#define OW0   0                 // float[192][64]
#define OWH   6144              // float[256][128]
#define OFEAT 22528             // u64 feat2[192][4]
#define OFSM  23296             // u64 fsm2[256][4]
#define ORED  24320             // u64 red[2048]
#define OMB   26368             // mbar: +0 f, +1 h
#define SMEM_BYTES ((OMB + 2) * 8)

__device__ __forceinline__ u64 pack2(float lo, float hi) {
    u64 r;
    asm("mov.b64 %0, {%1, %2};"
        : "=l"(r) : "r"(__float_as_uint(lo)), "r"(__float_as_uint(hi)));
    return r;
}
__device__ __forceinline__ void fma2(u64& d, u64 a, u64 b) {
    asm("fma.rn.f32x2 %0, %1, %2, %0;" : "+l"(d) : "l"(a), "l"(b));
}
__device__ __forceinline__ u64 add2(u64 a, u64 b) {
    u64 r;
    asm("add.rn.f32x2 %0, %1, %2;" : "=l"(r) : "l"(a), "l"(b));
    return r;
}
__device__ __forceinline__ float2 unpk(u64 v) {
    unsigned lo, hi;
    asm("mov.b64 {%0, %1}, %2;" : "=r"(lo), "=r"(hi) : "l"(v));
    return make_float2(__uint_as_float(lo), __uint_as_float(hi));
}
__device__ __forceinline__ unsigned smem_u32(const void* p) {
    unsigned a;
    asm("{ .reg .u64 t; cvta.to.shared.u64 t, %1; cvt.u32.u64 %0, t; }"
        : "=r"(a) : "l"(p));
    return a;
}
__device__ __forceinline__ unsigned mapa_rank(unsigned addr, unsigned rank) {
    unsigned r;
    asm("mapa.shared::cluster.u32 %0, %1, %2;" : "=r"(r) : "r"(addr), "r"(rank));
    return r;
}
__device__ __forceinline__ void st_cluster(unsigned addr, u64 v) {
    asm volatile("st.shared::cluster.b64 [%0], %1;" :: "r"(addr), "l"(v) : "memory");
}
__device__ __forceinline__ unsigned ctarank() {
    unsigned r;
    asm("mov.u32 %0, %%cluster_ctarank;" : "=r"(r));
    return r;
}
__device__ __forceinline__ void mbar_init(unsigned addr, unsigned cnt) {
    asm volatile("mbarrier.init.shared.b64 [%0], %1;" :: "r"(addr), "r"(cnt) : "memory");
}
__device__ __forceinline__ void mbar_arrive_remote(unsigned addr) {
    asm volatile("mbarrier.arrive.release.cluster.shared::cluster.b64 _, [%0];"
                 :: "r"(addr) : "memory");
}
__device__ __forceinline__ void mbar_wait(unsigned addr, unsigned parity) {
    asm volatile(
        "{\n\t.reg .pred P;\n"
        "W_%=:\n\t"
        "mbarrier.try_wait.parity.acquire.cluster.shared::cta.b64 P, [%0], %1, 0x989680;\n\t"
        "@P bra.uni D_%=;\n\t"
        "bra.uni W_%=;\n"
        "D_%=:\n\t}"
        :: "r"(addr), "r"(parity) : "memory");
}
#define CLUSTER_BAR() do { \
    asm volatile("barrier.cluster.arrive.aligned;" ::: "memory"); \
    asm volatile("barrier.cluster.wait.aligned;"   ::: "memory"); \
} while (0)

__global__ void __launch_bounds__(NTHRD, 1) __cluster_dims__(4, 1, 1)
cfc_kernel(
    const float* __restrict__ x_codes, const float* __restrict__ h0,
    const float* __restrict__ tsp,
    const float* __restrict__ W0, const float* __restrict__ b0,
    const float* __restrict__ W1, const float* __restrict__ b1,
    const float* __restrict__ W2, const float* __restrict__ b2,
    const float* __restrict__ Wa, const float* __restrict__ ba,
    const float* __restrict__ Wb, const float* __restrict__ bb,
    float* __restrict__ out)
{
    extern __shared__ u64 smu[];
    float* sW0 = (float*)(smu + OW0);
    float* sWH = (float*)(smu + OWH);
    u64* feat2 = smu + OFEAT;
    u64* fsm2  = smu + OFSM;
    u64* red   = smu + ORED;

    const int tid = threadIdx.x;
    const unsigned rank = ctarank();
    const int brow = (blockIdx.x >> 2) * 8;

    // ---- one-time weight / state loads ----
    for (int idx = tid; idx < 192 * 16; idx += NTHRD) {
        int k = idx >> 4, q = idx & 15;
        ((float4*)sW0)[idx] =
            *(const float4*)(W0 + (size_t)k * 256 + rank * 64 + q * 4);
    }
    for (int idx = tid; idx < 256 * 128; idx += NTHRD) {
        int k = idx >> 7, c = idx & 127, j = c >> 2, h = c & 3;
        const float* src = (h == 0 ? W1 : h == 1 ? W2 : h == 2 ? Wa : Wb);
        sWH[idx] = src[(size_t)k * 128 + 32 * rank + j];
    }
    for (int idx = tid; idx < 512; idx += NTHRD) {
        int u = idx & 127, rp = idx >> 7;
        feat2[(64 + u) * 4 + rp] = pack2(h0[(size_t)(brow + 2 * rp) * 128 + u],
                                         h0[(size_t)(brow + 2 * rp + 1) * 128 + u]);
    }
    const unsigned sbase = smem_u32(smu);
    const unsigned lfmb = sbase + (OMB + 0) * 8;
    const unsigned lhmb = sbase + (OMB + 1) * 8;
    if (tid == 0) {
        mbar_init(lfmb, 4 * 256);   // f: every thread of every CTA arrives
        mbar_init(lhmb, 4 * 128);   // h: gate threads of every CTA arrive
    }
    __syncthreads();
    CLUSTER_BAR();   // weights, h0, mbarrier inits visible cluster-wide

    // ---- remote addresses ----
    unsigned fsm_base[4], feat_base[4], fmb_r[4], hmb_r[4];
    {
        unsigned lf = smem_u32(fsm2), lh = smem_u32(feat2);
        #pragma unroll
        for (int r = 0; r < 4; ++r) {
            fsm_base[r]  = mapa_rank(lf, (unsigned)r);
            feat_base[r] = mapa_rank(lh, (unsigned)r);
            fmb_r[r]     = mapa_rank(lfmb, (unsigned)r);
            hmb_r[r]     = mapa_rank(lhmb, (unsigned)r);
        }
    }

    // ---- per-thread role constants ----
    const int cg  = tid & 31;
    const int k1b = (tid >> 5) * 24;
    const int col1 = tid & 63;
    const int rp1  = tid >> 6;
    const int gc1  = 64 * (int)rank + col1;
    const u64 b0d  = pack2(b0[gc1], b0[gc1]);
    const int cg2 = tid & 63;
    const int k2b = (tid >> 6) * 64;
    const float* wp2c = sWH + k2b * 128 + 2 * cg2;
    const u64* fp2c = fsm2 + k2b * 4;
    const int jg  = tid & 31;
    const int rpg = (tid >> 5) & 3;
    const int ug  = 32 * (int)rank + jg;
    const u64 b1d = pack2(b1[ug], b1[ug]);
    const u64 b2d = pack2(b2[ug], b2[ug]);
    const u64 bad = pack2(ba[ug], ba[ug]);
    const u64 bbd = pack2(bb[ug], bb[ug]);
    const int gr0 = brow + 2 * rpg;
    const float* tsa = tsp + (size_t)gr0 * S_LEN;
    const float* tsb = tsp + (size_t)(gr0 + 1) * S_LEN;
    float* outa = out + (size_t)gr0 * S_LEN * 128 + ug;
    float* outb = out + (size_t)(gr0 + 1) * S_LEN * 128 + ug;
    const int ch  = tid & 63;
    const int rpx = tid >> 6;
    const float* xa = x_codes + (size_t)(brow + 2 * rpx) * S_LEN * 64 + ch;
    const float* xb = x_codes + (size_t)(brow + 2 * rpx + 1) * S_LEN * 64 + ch;

    float2 wreg[KREG];
    #pragma unroll
    for (int k = 0; k < KREG; ++k) wreg[k] = *(const float2*)(wp2c + k * 128);

    float xr0 = xa[0], xr1 = xb[0];
    unsigned fpar = 0, hpar = 0;

    for (int s = 0; s < S_LEN; ++s) {
        float tsv0 = 0.f, tsv1 = 0.f;
        if (tid < 128) { tsv0 = tsa[s]; tsv1 = tsb[s]; }

        // wait for h(s-1) from all CTAs (skip at s=0: h0 primed + CLUSTER_BAR)
        if (s) { mbar_wait(lhmb, hpar); hpar ^= 1; }

        feat2[ch * 4 + rpx] = pack2((xr0 - 65.0f) * 0.01f, (xr1 - 65.0f) * 0.01f);
        __syncthreads();  // S1: feat (x + h) ready locally

        // ---- GEMM1 partials: 2 cols x 8 rows over 24 k ----
        u64 a00 = 0, a01 = 0, a02 = 0, a03 = 0;
        u64 a10 = 0, a11 = 0, a12 = 0, a13 = 0;
        {
            const float* wp = sW0 + k1b * 64 + 2 * cg;
            const u64* fp = feat2 + k1b * 4;
            #pragma unroll 12
            for (int k = 0; k < 24; ++k) {
                float2 w = *(const float2*)(wp + k * 64);
                u64 w0d = pack2(w.x, w.x), w1d = pack2(w.y, w.y);
                ulonglong2 f01 = *(const ulonglong2*)(fp + k * 4);
                ulonglong2 f23 = *(const ulonglong2*)(fp + k * 4 + 2);
                fma2(a00, f01.x, w0d); fma2(a01, f01.y, w0d);
                fma2(a02, f23.x, w0d); fma2(a03, f23.y, w0d);
                fma2(a10, f01.x, w1d); fma2(a11, f01.y, w1d);
                fma2(a12, f23.x, w1d); fma2(a13, f23.y, w1d);
            }
        }
        {
            u64* rb = red + (tid >> 5) * 256 + 2 * cg;   // [ks8][rp4][col64]
            *(ulonglong2*)(rb)       = make_ulonglong2(a00, a10);
            *(ulonglong2*)(rb + 64)  = make_ulonglong2(a01, a11);
            *(ulonglong2*)(rb + 128) = make_ulonglong2(a02, a12);
            *(ulonglong2*)(rb + 192) = make_ulonglong2(a03, a13);
        }
        __syncthreads();  // S2: red1 ready; all GEMM1 feat reads complete

        // ---- reduce1 + lecun_tanh + push f slice + arrive on all f-mbars ----
        {
            const u64* rr = red + rp1 * 64 + col1;
            u64 ssum = rr[0];
            #pragma unroll
            for (int q = 1; q < 8; ++q) ssum = add2(ssum, rr[q * 256]);
            ssum = add2(ssum, b0d);
            float2 v = unpk(ssum);
            u64 fv = pack2(1.7159f * tanhf(0.666f * v.x),
                           1.7159f * tanhf(0.666f * v.y));
            unsigned off = (unsigned)((gc1 * 4 + rp1) * 8);
            #pragma unroll
            for (int r = 0; r < 4; ++r) st_cluster(fsm_base[r] + off, fv);
            #pragma unroll
            for (int r = 0; r < 4; ++r) mbar_arrive_remote(fmb_r[r]);
        }
        if (s + 1 < S_LEN) { xr0 = xa[(size_t)(s + 1) * 64]; xr1 = xb[(size_t)(s + 1) * 64]; }

        mbar_wait(lfmb, fpar); fpar ^= 1;   // f(s) complete from all CTAs

        // ---- GEMM2: 2 cols x 8 rows over 64 k (48 reg + 16 smem weights) ----
        u64 q00 = 0, q01 = 0, q02 = 0, q03 = 0;
        u64 q10 = 0, q11 = 0, q12 = 0, q13 = 0;
        #pragma unroll
        for (int k = 0; k < KREG; ++k) {
            float2 w = wreg[k];
            u64 w0d = pack2(w.x, w.x), w1d = pack2(w.y, w.y);
            ulonglong2 f01 = *(const ulonglong2*)(fp2c + k * 4);
            ulonglong2 f23 = *(const ulonglong2*)(fp2c + k * 4 + 2);
            fma2(q00, f01.x, w0d); fma2(q01, f01.y, w0d);
            fma2(q02, f23.x, w0d); fma2(q03, f23.y, w0d);
            fma2(q10, f01.x, w1d); fma2(q11, f01.y, w1d);
            fma2(q12, f23.x, w1d); fma2(q13, f23.y, w1d);
        }
        #pragma unroll 8
        for (int k = KREG; k < 64; ++k) {
            float2 w = *(const float2*)(wp2c + k * 128);
            u64 w0d = pack2(w.x, w.x), w1d = pack2(w.y, w.y);
            ulonglong2 f01 = *(const ulonglong2*)(fp2c + k * 4);
            ulonglong2 f23 = *(const ulonglong2*)(fp2c + k * 4 + 2);
            fma2(q00, f01.x, w0d); fma2(q01, f01.y, w0d);
            fma2(q02, f23.x, w0d); fma2(q03, f23.y, w0d);
            fma2(q10, f01.x, w1d); fma2(q11, f01.y, w1d);
            fma2(q12, f23.x, w1d); fma2(q13, f23.y, w1d);
        }
        {
            u64* rb = red + (tid >> 6) * 512 + 2 * cg2;  // [ks4][rp4][col128]
            *(ulonglong2*)(rb)       = make_ulonglong2(q00, q10);
            *(ulonglong2*)(rb + 128) = make_ulonglong2(q01, q11);
            *(ulonglong2*)(rb + 256) = make_ulonglong2(q02, q12);
            *(ulonglong2*)(rb + 384) = make_ulonglong2(q03, q13);
        }
        __syncthreads();  // S3: red2 ready

        // ---- gate: reduce, sigmoid blend, out, h-push + arrive h-mbars ----
        if (tid < 128) {
            const u64* rr = red + rpg * 128 + 4 * jg;
            ulonglong2 g0 = *(const ulonglong2*)(rr);
            ulonglong2 g1 = *(const ulonglong2*)(rr + 2);
            u64 p1 = g0.x, p2 = g0.y, pa = g1.x, pb = g1.y;
            #pragma unroll
            for (int q = 1; q < 4; ++q) {
                ulonglong2 h0v = *(const ulonglong2*)(rr + q * 512);
                ulonglong2 h1v = *(const ulonglong2*)(rr + q * 512 + 2);
                p1 = add2(p1, h0v.x); p2 = add2(p2, h0v.y);
                pa = add2(pa, h1v.x); pb = add2(pb, h1v.y);
            }
            p1 = add2(p1, b1d); p2 = add2(p2, b2d);
            pa = add2(pa, bad); pb = add2(pb, bbd);
            float2 f1v = unpk(p1), f2v = unpk(p2), av = unpk(pa), bv = unpk(pb);
            float ti0 = 1.0f / (1.0f + expf(av.x * tsv0 - bv.x));
            float ti1 = 1.0f / (1.0f + expf(av.y * tsv1 - bv.y));
            float nh0 = f1v.x + ti0 * (f2v.x - f1v.x);
            float nh1 = f1v.y + ti1 * (f2v.y - f1v.y);
            outa[(size_t)s * 128] = nh0;
            outb[(size_t)s * 128] = nh1;
            // Skip h exchange on the final step: nobody consumes h(S-1), and
            // skipping guarantees no inbound remote op can target an exited CTA.
            if (s + 1 < S_LEN) {
                u64 hv = pack2(nh0, nh1);
                unsigned off = (unsigned)(((64 + ug) * 4 + rpg) * 8);
                #pragma unroll
                for (int r = 0; r < 4; ++r) st_cluster(feat_base[r] + off, hv);
                #pragma unroll
                for (int r = 0; r < 4; ++r) mbar_arrive_remote(hmb_r[r]);
            }
        }
        // no trailing barrier: next step's h-wait provides the cross-CTA sync
    }

    // Exit safety: ensure all CTAs (and any straggling remote ops) are done
    // before any CTA's SMEM is deallocated.
    CLUSTER_BAR();
}

extern "C" void kernel_launch(void* const* d_in, const int* in_sizes, int n_in,
                              void* d_out, int out_size) {
    const float* x_codes = (const float*)d_in[0];
    const float* h0      = (const float*)d_in[1];
    const float* tsp     = (const float*)d_in[2];
    const float* W0      = (const float*)d_in[3];
    const float* b0      = (const float*)d_in[4];
    const float* W1      = (const float*)d_in[5];
    const float* b1      = (const float*)d_in[6];
    const float* W2      = (const float*)d_in[7];
    const float* b2      = (const float*)d_in[8];
    const float* Wa      = (const float*)d_in[9];
    const float* ba      = (const float*)d_in[10];
    const float* Wb      = (const float*)d_in[11];
    const float* bb      = (const float*)d_in[12];
    float* out = (float*)d_out;

    cudaFuncSetAttribute(cfc_kernel,
                         cudaFuncAttributeMaxDynamicSharedMemorySize, SMEM_BYTES);

    cfc_kernel<<<128, NTHRD, SMEM_BYTES>>>(
        x_codes, h0, tsp, W0, b0, W1, b1, W2, b2, Wa, ba, Wb, bb, out);
}

// round 15
// speedup vs baseline: 1.1978x; 1.1978x over previous
#include <cuda_runtime.h>

// CfC recurrent kernel, round 15: two-stream software pipeline over the R11
// 4-CTA-cluster design using split barrier.cluster.arrive/wait so each
// barrier wait is overlapped by a GEMM phase of the other stream.
// B=256, S=2048, C=64, U=128, H=256. 32 clusters x 4 CTAs x 256 threads;
// cluster owns 8 rows = stream A (rows 0-3) + stream B (rows 4-7).
// CTA rank holds W0[:,64r:+64) + interleaved head quads for units [32r,+32);
// 48/64 GEMM2 k-slices register-pinned (shared by both streams).

typedef unsigned long long u64;

#define S_LEN 2048
#define NTHRD 256
#define KREG 48

// SMEM layout (u64 units)
#define OW0 0          // float[192][64]   6144
#define OWH 6144       // float[256][128]  16384
#define OFA 22528      // featA u64[192][2]
#define OFB 22912      // featB u64[192][2]
#define OSA 23296      // fsmA  u64[256][2]
#define OSB 23808      // fsmB  u64[256][2]
#define ORA 24320      // redA  u64[1024]
#define ORB 25344      // redB  u64[1024]
#define OTOT 26368
#define SMEM_BYTES (OTOT * 8)

__device__ __forceinline__ u64 pack2(float lo, float hi) {
    u64 r;
    asm("mov.b64 %0, {%1, %2};"
        : "=l"(r) : "r"(__float_as_uint(lo)), "r"(__float_as_uint(hi)));
    return r;
}
__device__ __forceinline__ void fma2(u64& d, u64 a, u64 b) {
    asm("fma.rn.f32x2 %0, %1, %2, %0;" : "+l"(d) : "l"(a), "l"(b));
}
__device__ __forceinline__ u64 add2(u64 a, u64 b) {
    u64 r;
    asm("add.rn.f32x2 %0, %1, %2;" : "=l"(r) : "l"(a), "l"(b));
    return r;
}
__device__ __forceinline__ float2 unpk(u64 v) {
    unsigned lo, hi;
    asm("mov.b64 {%0, %1}, %2;" : "=r"(lo), "=r"(hi) : "l"(v));
    return make_float2(__uint_as_float(lo), __uint_as_float(hi));
}
__device__ __forceinline__ unsigned smem_u32(const void* p) {
    unsigned a;
    asm("{ .reg .u64 t; cvta.to.shared.u64 t, %1; cvt.u32.u64 %0, t; }"
        : "=r"(a) : "l"(p));
    return a;
}
__device__ __forceinline__ unsigned mapa_rank(unsigned addr, unsigned rank) {
    unsigned r;
    asm("mapa.shared::cluster.u32 %0, %1, %2;" : "=r"(r) : "r"(addr), "r"(rank));
    return r;
}
__device__ __forceinline__ void st_cluster(unsigned addr, u64 v) {
    asm volatile("st.shared::cluster.b64 [%0], %1;" :: "r"(addr), "l"(v) : "memory");
}
__device__ __forceinline__ unsigned ctarank() {
    unsigned r;
    asm("mov.u32 %0, %%cluster_ctarank;" : "=r"(r));
    return r;
}
#define CBAR_ARRIVE() asm volatile("barrier.cluster.arrive.aligned;" ::: "memory")
#define CBAR_WAIT()   asm volatile("barrier.cluster.wait.aligned;"   ::: "memory")

__global__ void __launch_bounds__(NTHRD, 1) __cluster_dims__(4, 1, 1)
cfc_kernel(
    const float* __restrict__ x_codes, const float* __restrict__ h0,
    const float* __restrict__ tsp,
    const float* __restrict__ W0, const float* __restrict__ b0,
    const float* __restrict__ W1, const float* __restrict__ b1,
    const float* __restrict__ W2, const float* __restrict__ b2,
    const float* __restrict__ Wa, const float* __restrict__ ba,
    const float* __restrict__ Wb, const float* __restrict__ bb,
    float* __restrict__ out)
{
    extern __shared__ u64 smu[];
    float* sW0 = (float*)(smu + OW0);
    float* sWH = (float*)(smu + OWH);
    u64* featA = smu + OFA;
    u64* featB = smu + OFB;
    u64* fsmA  = smu + OSA;
    u64* fsmB  = smu + OSB;
    u64* redA  = smu + ORA;
    u64* redB  = smu + ORB;

    const int tid = threadIdx.x;
    const unsigned rank = ctarank();
    const int brow = (blockIdx.x >> 2) * 8;   // A: brow..+3, B: brow+4..+7

    // ---- one-time weight loads ----
    for (int idx = tid; idx < 192 * 16; idx += NTHRD) {
        int k = idx >> 4, q = idx & 15;
        ((float4*)sW0)[idx] =
            *(const float4*)(W0 + (size_t)k * 256 + rank * 64 + q * 4);
    }
    for (int idx = tid; idx < 256 * 128; idx += NTHRD) {
        int k = idx >> 7, c = idx & 127, j = c >> 2, h = c & 3;
        const float* src = (h == 0 ? W1 : h == 1 ? W2 : h == 2 ? Wa : Wb);
        sWH[idx] = src[(size_t)k * 128 + 32 * rank + j];
    }
    // ---- h0 priming for both streams ----
    for (int idx = tid; idx < 512; idx += NTHRD) {
        int st = idx >> 8, u = idx & 127, rp = (idx >> 7) & 1;
        int r0 = brow + 4 * st + 2 * rp;
        u64* f = st ? featB : featA;
        f[(64 + u) * 2 + rp] =
            pack2(h0[(size_t)r0 * 128 + u], h0[(size_t)(r0 + 1) * 128 + u]);
    }

    // ---- role constants ----
    const int cg  = tid & 31;            // GEMM1: 2 cols
    const int k1b = (tid >> 5) * 24;     // GEMM1: 8 k-groups of 24
    const int col1 = tid & 63;           // reduce: col (both halves)
    const int rp1  = (tid >> 6) & 1;     // reduce: row-pair
    const int gc1  = 64 * (int)rank + col1;
    const u64 b0d  = pack2(b0[gc1], b0[gc1]);
    const int cg2 = tid & 63;            // GEMM2: 2 cols
    const int k2b = (tid >> 6) * 64;     // GEMM2: 4 k-groups of 64
    const float* wp2c = sWH + k2b * 128 + 2 * cg2;
    // gate (tid<64): 32 units x 2 row-pairs
    const int jg  = tid & 31;
    const int rpg = (tid >> 5) & 1;
    const int ug  = 32 * (int)rank + jg;
    const u64 b1d = pack2(b1[ug], b1[ug]);
    const u64 b2d = pack2(b2[ug], b2[ug]);
    const u64 bad = pack2(ba[ug], ba[ug]);
    const u64 bbd = pack2(bb[ug], bb[ug]);
    const int grA = brow + 2 * rpg;          // gate rows stream A
    const int grB = brow + 4 + 2 * rpg;      // gate rows stream B
    const float* tsA0 = tsp + (size_t)grA * S_LEN;
    const float* tsA1 = tsp + (size_t)(grA + 1) * S_LEN;
    const float* tsB0 = tsp + (size_t)grB * S_LEN;
    const float* tsB1 = tsp + (size_t)(grB + 1) * S_LEN;
    float* outA0 = out + (size_t)grA * S_LEN * 128 + ug;
    float* outA1 = out + (size_t)(grA + 1) * S_LEN * 128 + ug;
    float* outB0 = out + (size_t)grB * S_LEN * 128 + ug;
    float* outB1 = out + (size_t)(grB + 1) * S_LEN * 128 + ug;
    // x loader: tid>=128 -> stream A; tid<128 -> stream B
    const int xt  = tid & 127;
    const int ch  = xt & 63;
    const int rpx = (xt >> 6) & 1;
    const int xrow = (tid >= 128 ? brow : brow + 4) + 2 * rpx;
    const float* xp0 = x_codes + (size_t)xrow * S_LEN * 64 + ch;
    const float* xp1 = x_codes + (size_t)(xrow + 1) * S_LEN * 64 + ch;
    u64* featX = (tid >= 128) ? featA : featB;

    // x(0) for both streams + prefetch x(1)
    featX[ch * 2 + rpx] = pack2((xp0[0] - 65.0f) * 0.01f, (xp1[0] - 65.0f) * 0.01f);
    float xr0 = xp0[64], xr1 = xp1[64];

    __syncthreads();
    CBAR_ARRIVE(); CBAR_WAIT();   // weights, h0, x(0) visible cluster-wide

    // ---- remote push bases ----
    unsigned fsmA_r[4], fsmB_r[4], featA_r[4], featB_r[4];
    {
        unsigned la = smem_u32(fsmA), lb = smem_u32(fsmB);
        unsigned fa = smem_u32(featA), fb = smem_u32(featB);
        #pragma unroll
        for (int r = 0; r < 4; ++r) {
            fsmA_r[r]  = mapa_rank(la, (unsigned)r);
            fsmB_r[r]  = mapa_rank(lb, (unsigned)r);
            featA_r[r] = mapa_rank(fa, (unsigned)r);
            featB_r[r] = mapa_rank(fb, (unsigned)r);
        }
    }

    float2 wreg[KREG];
    #pragma unroll
    for (int k = 0; k < KREG; ++k) wreg[k] = *(const float2*)(wp2c + k * 128);

    // GEMM1 partial for one stream: 2 cols x 2 rps over 24 k
    #define GEMM1(FEATX, REDX) do {                                           \
        u64 a00 = 0, a01 = 0, a10 = 0, a11 = 0;                               \
        const float* wp = sW0 + k1b * 64 + 2 * cg;                            \
        const u64* fp = (FEATX) + k1b * 2;                                    \
        _Pragma("unroll")                                                     \
        for (int k = 0; k < 24; ++k) {                                        \
            float2 w = *(const float2*)(wp + k * 64);                         \
            u64 w0 = pack2(w.x, w.x), w1 = pack2(w.y, w.y);                   \
            ulonglong2 f = *(const ulonglong2*)(fp + k * 2);                  \
            fma2(a00, f.x, w0); fma2(a01, f.y, w0);                           \
            fma2(a10, f.x, w1); fma2(a11, f.y, w1);                           \
        }                                                                     \
        u64* rb = (REDX) + (tid >> 5) * 128 + 2 * cg;                         \
        *(ulonglong2*)(rb)      = make_ulonglong2(a00, a10);                  \
        *(ulonglong2*)(rb + 64) = make_ulonglong2(a01, a11);                  \
    } while (0)

    #define REDUCE_PUSH_F(REDX, BASES) do {                                   \
        const u64* rr = (REDX) + rp1 * 64 + col1;                             \
        u64 ss = rr[0];                                                       \
        _Pragma("unroll")                                                     \
        for (int q = 1; q < 8; ++q) ss = add2(ss, rr[q * 128]);               \
        ss = add2(ss, b0d);                                                   \
        float2 v = unpk(ss);                                                  \
        u64 fv = pack2(1.7159f * tanhf(0.666f * v.x),                         \
                       1.7159f * tanhf(0.666f * v.y));                        \
        unsigned off = (unsigned)((gc1 * 2 + rp1) * 8);                       \
        _Pragma("unroll")                                                     \
        for (int r = 0; r < 4; ++r) st_cluster((BASES)[r] + off, fv);         \
    } while (0)

    #define GEMM2(FSMX, REDX) do {                                           \
        u64 q00 = 0, q01 = 0, q10 = 0, q11 = 0;                               \
        const u64* fp2 = (FSMX) + k2b * 2;                                    \
        _Pragma("unroll")                                                     \
        for (int k = 0; k < KREG; ++k) {                                      \
            float2 w = wreg[k];                                               \
            u64 w0 = pack2(w.x, w.x), w1 = pack2(w.y, w.y);                   \
            ulonglong2 f = *(const ulonglong2*)(fp2 + k * 2);                 \
            fma2(q00, f.x, w0); fma2(q01, f.y, w0);                           \
            fma2(q10, f.x, w1); fma2(q11, f.y, w1);                           \
        }                                                                     \
        _Pragma("unroll") \
        for (int k = KREG; k < 64; ++k) {                                     \
            float2 w = *(const float2*)(wp2c + k * 128);                      \
            u64 w0 = pack2(w.x, w.x), w1 = pack2(w.y, w.y);                   \
            ulonglong2 f = *(const ulonglong2*)(fp2 + k * 2);                 \
            fma2(q00, f.x, w0); fma2(q01, f.y, w0);                           \
            fma2(q10, f.x, w1); fma2(q11, f.y, w1);                           \
        }                                                                     \
        u64* rb = (REDX) + (tid >> 6) * 256 + 2 * cg2;                        \
        *(ulonglong2*)(rb)       = make_ulonglong2(q00, q10);                 \
        *(ulonglong2*)(rb + 128) = make_ulonglong2(q01, q11);                 \
    } while (0)

    #define GATE(REDX, T0, T1, O0, O1, FBASES, PUSH) do {                     \
        const u64* rr = (REDX) + rpg * 128 + 4 * jg;                          \
        ulonglong2 g0 = *(const ulonglong2*)(rr);                             \
        ulonglong2 g1 = *(const ulonglong2*)(rr + 2);                         \
        u64 p1 = g0.x, p2 = g0.y, pa = g1.x, pb = g1.y;                       \
        _Pragma("unroll")                                                     \
        for (int q = 1; q < 4; ++q) {                                         \
            ulonglong2 u0 = *(const ulonglong2*)(rr + q * 256);               \
            ulonglong2 u1 = *(const ulonglong2*)(rr + q * 256 + 2);           \
            p1 = add2(p1, u0.x); p2 = add2(p2, u0.y);                         \
            pa = add2(pa, u1.x); pb = add2(pb, u1.y);                         \
        }                                                                     \
        p1 = add2(p1, b1d); p2 = add2(p2, b2d);                               \
        pa = add2(pa, bad); pb = add2(pb, bbd);                               \
        float2 f1 = unpk(p1), f2 = unpk(p2), av = unpk(pa), bv = unpk(pb);    \
        float ti0 = 1.0f / (1.0f + expf(av.x * (T0) - bv.x));                 \
        float ti1 = 1.0f / (1.0f + expf(av.y * (T1) - bv.y));                 \
        float nh0 = f1.x + ti0 * (f2.x - f1.x);                               \
        float nh1 = f1.y + ti1 * (f2.y - f1.y);                               \
        (O0)[(size_t)s * 128] = nh0;                                          \
        (O1)[(size_t)s * 128] = nh1;                                          \
        if (PUSH) {                                                           \
            u64 hv = pack2(nh0, nh1);                                         \
            unsigned off = (unsigned)(((64 + ug) * 2 + rpg) * 8);             \
            _Pragma("unroll")                                                 \
            for (int r = 0; r < 4; ++r) st_cluster((FBASES)[r] + off, hv);    \
        }                                                                     \
    } while (0)

    for (int s = 0; s < S_LEN; ++s) {
        float tA0 = 0.f, tA1 = 0.f, tB0 = 0.f, tB1 = 0.f;
        if (tid < 64) {
            tA0 = tsA0[s]; tA1 = tsA1[s];
            tB0 = tsB0[s]; tB1 = tsB1[s];
        }

        // ---- GEMM1 A (featA: hA via g3(s-1) wait; xA(s) local) ----
        GEMM1(featA, redA);
        __syncthreads();                          // SA: red1A ready

        if (s) CBAR_WAIT();                       // g4(s-1): hB + all bufs safe
        if (tid < 128) {
            REDUCE_PUSH_F(redA, fsmA_r);          // push fA(s) to all CTAs
        } else if (s + 1 < S_LEN) {
            featX[ch * 2 + rpx] =                 // xA(s+1) into featA
                pack2((xr0 - 65.0f) * 0.01f, (xr1 - 65.0f) * 0.01f);
            if (s + 2 < S_LEN) { xr0 = xp0[(size_t)(s + 2) * 64]; xr1 = xp1[(size_t)(s + 2) * 64]; }
        }
        CBAR_ARRIVE();                            // g1: fA pushed

        // ---- GEMM1 B (featB: hB via g4(s-1); xB(s) local) ----
        GEMM1(featB, redB);
        __syncthreads();                          // SB: red1B ready

        CBAR_WAIT();                              // g1: fsmA complete
        if (tid >= 128) {
            REDUCE_PUSH_F(redB, fsmB_r);          // push fB(s)
        } else if (s + 1 < S_LEN) {
            featX[ch * 2 + rpx] =                 // xB(s+1) into featB
                pack2((xr0 - 65.0f) * 0.01f, (xr1 - 65.0f) * 0.01f);
            if (s + 2 < S_LEN) { xr0 = xp0[(size_t)(s + 2) * 64]; xr1 = xp1[(size_t)(s + 2) * 64]; }
        }
        CBAR_ARRIVE();                            // g2: fB pushed

        // ---- GEMM2 A (fsmA ready via g1) ----
        GEMM2(fsmA, redA);
        __syncthreads();                          // SC: red2A ready

        CBAR_WAIT();                              // g2: fsmB complete
        if (tid < 64)
            GATE(redA, tA0, tA1, outA0, outA1, featA_r, (s + 1 < S_LEN));
        CBAR_ARRIVE();                            // g3: hA pushed

        // ---- GEMM2 B (fsmB ready via g2) ----
        GEMM2(fsmB, redB);
        __syncthreads();                          // SD: red2B ready

        CBAR_WAIT();                              // g3: hA delivered (next GEMM1A)
        if (tid < 64)
            GATE(redB, tB0, tB1, outB0, outB1, featB_r, (s + 1 < S_LEN));
        CBAR_ARRIVE();                            // g4: hB pushed
    }

    CBAR_WAIT();   // final g4: all inbound remote ops complete before exit
}

extern "C" void kernel_launch(void* const* d_in, const int* in_sizes, int n_in,
                              void* d_out, int out_size) {
    const float* x_codes = (const float*)d_in[0];
    const float* h0      = (const float*)d_in[1];
    const float* tsp     = (const float*)d_in[2];
    const float* W0      = (const float*)d_in[3];
    const float* b0      = (const float*)d_in[4];
    const float* W1      = (const float*)d_in[5];
    const float* b1      = (const float*)d_in[6];
    const float* W2      = (const float*)d_in[7];
    const float* b2      = (const float*)d_in[8];
    const float* Wa      = (const float*)d_in[9];
    const float* ba      = (const float*)d_in[10];
    const float* Wb      = (const float*)d_in[11];
    const float* bb      = (const float*)d_in[12];
    float* out = (float*)d_out;

    cudaFuncSetAttribute(cfc_kernel,
                         cudaFuncAttributeMaxDynamicSharedMemorySize, SMEM_BYTES);

    cfc_kernel<<<128, NTHRD, SMEM_BYTES>>>(
        x_codes, h0, tsp, W0, b0, W1, b1, W2, b2, Wa, ba, Wb, bb, out);
}